// round 3
// baseline (speedup 1.0000x reference)
#include <cuda_runtime.h>

#define BDIM 128
#define HDIM 32
#define SDIM 64
#define DDIM 128
#define STARTLEN 32
#define G 4
#define NT 256
#define BSTR (HDIM * SDIM * DDIM)        // batch stride in k/v arrays (floats)

// SMEM layout (float offsets), total 6912 floats = 27648 B  -> 3 CTAs/SM
#define XST 0                            // [128][4] x transposed (batch-packed float4)
#define QS  512                          // [4][128] q (scale folded in)
#define ATT 1024                         // [4][64]
#define AOP 1280                         // [2][4][128] AV partials (s-halves)
#define AOT 2304                         // [128][4] attention out transposed
#define RED 2816                         // [32][128] projection partials
#define SMEM_FLOATS 6912

__global__ void __launch_bounds__(NT, 3)
attn_decode_kernel(const float* __restrict__ x_in,
                   const float* __restrict__ k_in,
                   const float* __restrict__ v_in,
                   const float* __restrict__ wq,
                   const float* __restrict__ wk,
                   const float* __restrict__ wv,
                   const float* __restrict__ wo,
                   float* k_out, float* v_out, float* __restrict__ x_out)
{
    __shared__ float sm[SMEM_FLOATS];

    const int t = threadIdx.x;
    const int w = t >> 5;
    const int l = t & 31;
    const int h  = blockIdx.x >> 5;          // 32 batch-groups per head
    const int b0 = (blockIdx.x & 31) * G;

    float* kg = k_out + (size_t)(b0 * HDIM + h) * (SDIM * DDIM);
    float* vg = v_out + (size_t)(b0 * HDIM + h) * (SDIM * DDIM);

    // ---- prologue: k_in->k_out, v_in->v_out (write-through caches), x -> xsT ----
    {
        const float* kin = k_in + (size_t)(b0 * HDIM + h) * (SDIM * DDIM);
        const float* vin = v_in + (size_t)(b0 * HDIM + h) * (SDIM * DDIM);
        #pragma unroll
        for (int b = 0; b < G; ++b) {
            const float4* ks = (const float4*)(kin + (size_t)b * BSTR);
            const float4* vs = (const float4*)(vin + (size_t)b * BSTR);
            float4* kd = (float4*)(kg + (size_t)b * BSTR);
            float4* vd = (float4*)(vg + (size_t)b * BSTR);
            for (int i = t; i < SDIM * DDIM / 4; i += NT) {
                kd[i] = ks[i];
                vd[i] = vs[i];
            }
        }
        for (int i = t; i < G * DDIM; i += NT) {
            int b = i >> 7, e = i & 127;
            sm[XST + e * 4 + b] = x_in[(size_t)((b0 + b) * HDIM + h) * DDIM + e];
        }
    }
    __syncthreads();

    const float4* Wq4 = (const float4*)(wq + (size_t)h * DDIM * DDIM);
    const float4* Wk4 = (const float4*)(wk + (size_t)h * DDIM * DDIM);
    const float4* Wv4 = (const float4*)(wv + (size_t)h * DDIM * DDIM);
    const float4* Wo4 = (const float4*)(wo + (size_t)h * DDIM * DDIM);

    // P1 task split: warps 0-1 q (d-halves), 2-3 k (d-halves), 4-7 v (d-quarters)
    const float4* Wp;
    int p_d0, p_nd, p_row;
    if (w < 2)      { Wp = Wq4; p_d0 = (w & 1) * 64;  p_nd = 64; p_row = w; }
    else if (w < 4) { Wp = Wk4; p_d0 = (w & 1) * 64;  p_nd = 64; p_row = w; }
    else            { Wp = Wv4; p_d0 = (w & 3) * 32;  p_nd = 32; p_row = w; }

    for (int gen = STARTLEN; gen < SDIM; ++gen) {
        // ===== P1: QKV projections, all 8 warps, 4 batches per weight load =====
        {
            float4 a0 = {0,0,0,0}, a1 = {0,0,0,0}, a2 = {0,0,0,0}, a3 = {0,0,0,0};
            #pragma unroll 8
            for (int dd = 0; dd < p_nd; ++dd) {
                int d = p_d0 + dd;
                float4 wv4 = Wp[d * 32 + l];                 // LDG.128, L2
                float4 x4  = *(const float4*)(sm + XST + d * 4);  // LDS.128 bcast
                a0.x += x4.x * wv4.x; a0.y += x4.x * wv4.y; a0.z += x4.x * wv4.z; a0.w += x4.x * wv4.w;
                a1.x += x4.y * wv4.x; a1.y += x4.y * wv4.y; a1.z += x4.y * wv4.z; a1.w += x4.y * wv4.w;
                a2.x += x4.z * wv4.x; a2.y += x4.z * wv4.y; a2.z += x4.z * wv4.z; a2.w += x4.z * wv4.w;
                a3.x += x4.w * wv4.x; a3.y += x4.w * wv4.y; a3.z += x4.w * wv4.z; a3.w += x4.w * wv4.w;
            }
            // rows: q,k -> (w*4+b) in [0,16); v -> ((4+dq)*4+b) in [16,32)
            int base = (w < 4) ? (w * 4) : ((4 + (w & 3)) * 4);
            *(float4*)(sm + RED + (base + 0) * 128 + 4 * l) = a0;
            *(float4*)(sm + RED + (base + 1) * 128 + 4 * l) = a1;
            *(float4*)(sm + RED + (base + 2) * 128 + 4 * l) = a2;
            *(float4*)(sm + RED + (base + 3) * 128 + 4 * l) = a3;
        }
        __syncthreads();

        // ===== reduce partials -> qs (smem), K[gen] & V[gen] (global write-through) =====
        #pragma unroll
        for (int i = 0; i < 6; ++i) {
            int o = i * NT + t;              // 0..1535
            int m = o >> 9;                  // 0=q,1=k,2=v
            int b = (o >> 7) & 3;
            int e = o & 127;
            float val;
            if (m < 2) {
                val = sm[RED + ((m * 2 + 0) * 4 + b) * 128 + e]
                    + sm[RED + ((m * 2 + 1) * 4 + b) * 128 + e];
            } else {
                val = sm[RED + (16 + 0 * 4 + b) * 128 + e]
                    + sm[RED + (16 + 1 * 4 + b) * 128 + e]
                    + sm[RED + (16 + 2 * 4 + b) * 128 + e]
                    + sm[RED + (16 + 3 * 4 + b) * 128 + e];
            }
            if (m == 0)      sm[QS + b * 128 + e] = val * 0.125f;   // fold scale into q
            else if (m == 1) kg[(size_t)b * BSTR + gen * DDIM + e] = val;
            else             vg[(size_t)b * BSTR + gen * DDIM + e] = val;
        }
        __syncthreads();

        // ===== P2: QK scores. warp = (batch, s-half); lanes over d; shuffle reduce =====
        {
            const int bb = w >> 1, hs = w & 1;
            const float4* kb4 = (const float4*)(kg + (size_t)bb * BSTR);
            float4 q4 = *(const float4*)(sm + QS + bb * 128 + 4 * l);
            #pragma unroll 4
            for (int r = 0; r < 32; ++r) {
                int s = hs * 32 + r;
                float4 k4 = kb4[s * 32 + l];
                float p = k4.x * q4.x + k4.y * q4.y + k4.z * q4.z + k4.w * q4.w;
                #pragma unroll
                for (int o = 16; o > 0; o >>= 1) p += __shfl_xor_sync(0xFFFFFFFFu, p, o);
                if (l == 0) sm[ATT + bb * 64 + s] = p;
            }
        }
        __syncthreads();

        // ===== P3: softmax, warp per batch =====
        if (w < 4) {
            float s0 = sm[ATT + w * 64 + l];
            float s1 = sm[ATT + w * 64 + 32 + l];
            float mx = fmaxf(s0, s1);
            #pragma unroll
            for (int o = 16; o > 0; o >>= 1) mx = fmaxf(mx, __shfl_xor_sync(0xFFFFFFFFu, mx, o));
            float e0 = __expf(s0 - mx);
            float e1 = __expf(s1 - mx);
            float su = e0 + e1;
            #pragma unroll
            for (int o = 16; o > 0; o >>= 1) su += __shfl_xor_sync(0xFFFFFFFFu, su, o);
            float inv = 1.0f / su;
            sm[ATT + w * 64 + l]      = e0 * inv;
            sm[ATT + w * 64 + 32 + l] = e1 * inv;
        }
        __syncthreads();

        // ===== P4: AV. warp = (batch, s-half); lanes over d (float4); V from L2 =====
        {
            const int bb = w >> 1, sh = w & 1;
            const float4* vb4 = (const float4*)(vg + (size_t)bb * BSTR);
            float4 acc = {0,0,0,0};
            #pragma unroll 8
            for (int i = 0; i < 32; ++i) {
                int s = sh * 32 + i;
                float a = sm[ATT + bb * 64 + s];
                float4 v4 = vb4[s * 32 + l];
                acc.x += a * v4.x; acc.y += a * v4.y; acc.z += a * v4.z; acc.w += a * v4.w;
            }
            *(float4*)(sm + AOP + sh * 512 + bb * 128 + 4 * l) = acc;
        }
        __syncthreads();

        // ===== mini-reduce: aoP -> aoT[d][4] (transposed, batch-packed) =====
        if (t < 128) {
            float4 r;
            r.x = sm[AOP + 0 * 128 + t] + sm[AOP + 512 + 0 * 128 + t];
            r.y = sm[AOP + 1 * 128 + t] + sm[AOP + 512 + 1 * 128 + t];
            r.z = sm[AOP + 2 * 128 + t] + sm[AOP + 512 + 2 * 128 + t];
            r.w = sm[AOP + 3 * 128 + t] + sm[AOP + 512 + 3 * 128 + t];
            *(float4*)(sm + AOT + t * 4) = r;
        }
        __syncthreads();

        // ===== P5: O projection. warp = (d-quarter, batch-pair); 2 batches/warp =====
        {
            const int dq = w & 3, bp = w >> 2;
            float4 a0 = {0,0,0,0}, a1 = {0,0,0,0};
            #pragma unroll 8
            for (int dd = 0; dd < 32; ++dd) {
                int d = dq * 32 + dd;
                float4 wv4 = Wo4[d * 32 + l];
                float4 x4  = *(const float4*)(sm + AOT + d * 4);
                float xa = bp ? x4.z : x4.x;
                float xb = bp ? x4.w : x4.y;
                a0.x += xa * wv4.x; a0.y += xa * wv4.y; a0.z += xa * wv4.z; a0.w += xa * wv4.w;
                a1.x += xb * wv4.x; a1.y += xb * wv4.y; a1.z += xb * wv4.z; a1.w += xb * wv4.w;
            }
            *(float4*)(sm + RED + ((bp * 4 + dq) * 2 + 0) * 128 + 4 * l) = a0;
            *(float4*)(sm + RED + ((bp * 4 + dq) * 2 + 1) * 128 + 4 * l) = a1;
        }
        __syncthreads();

        // ===== reduce 4 d-quarters -> new x (transposed) =====
        #pragma unroll
        for (int i = 0; i < 2; ++i) {
            int o = i * NT + t;
            int b = o >> 7, e = o & 127;
            int bp = b >> 1, j = b & 1;
            float v = sm[RED + ((bp * 4 + 0) * 2 + j) * 128 + e]
                    + sm[RED + ((bp * 4 + 1) * 2 + j) * 128 + e]
                    + sm[RED + ((bp * 4 + 2) * 2 + j) * 128 + e]
                    + sm[RED + ((bp * 4 + 3) * 2 + j) * 128 + e];
            sm[XST + e * 4 + b] = v;
        }
        __syncthreads();
    }

    // ---- epilogue: only x remains (k/v already written through) ----
    for (int i = t; i < G * DDIM; i += NT) {
        int b = i >> 7, e = i & 127;
        x_out[(size_t)((b0 + b) * HDIM + h) * DDIM + e] = sm[XST + e * 4 + b];
    }
}

extern "C" void kernel_launch(void* const* d_in, const int* in_sizes, int n_in,
                              void* d_out, int out_size)
{
    const float* x  = (const float*)d_in[0];
    const float* k  = (const float*)d_in[1];
    const float* v  = (const float*)d_in[2];
    const float* wq = (const float*)d_in[3];
    const float* wk = (const float*)d_in[4];
    const float* wv = (const float*)d_in[5];
    const float* wo = (const float*)d_in[6];

    float* out   = (float*)d_out;
    float* k_out = out;
    float* v_out = out + (size_t)BDIM * HDIM * SDIM * DDIM;
    float* x_out = out + (size_t)2 * BDIM * HDIM * SDIM * DDIM;

    attn_decode_kernel<<<BDIM * HDIM / G, NT>>>(
        x, k, v, wq, wk, wv, wo, k_out, v_out, x_out);
}